// round 5
// baseline (speedup 1.0000x reference)
#include <cuda_runtime.h>
#include <cuda_bf16.h>
#include <cstdint>

#define D 128
#define TILE_ROWS 96
#define FUSED_THREADS 384

typedef unsigned long long ull;

// -------- scratch (no cudaMalloc allowed) --------
#define MAX_NODES 100000
#define MAX_EDGES 1600000
__device__ float g_xA[(size_t)MAX_NODES * D];
__device__ float g_xB[(size_t)MAX_NODES * D];
__device__ int   g_counts[MAX_NODES];
__device__ int   g_offs[MAX_NODES + 1];
__device__ int   g_cursor[MAX_NODES];
__device__ int   g_csr_src[MAX_EDGES];

// -------- packed fp32x2 helpers (Blackwell FFMA2) --------
__device__ __forceinline__ ull pack2(float lo, float hi) {
    ull r; asm("mov.b64 %0, {%1,%2};" : "=l"(r) : "f"(lo), "f"(hi)); return r;
}
__device__ __forceinline__ void fma2(ull &d, ull a, ull b) {
    asm("fma.rn.f32x2 %0, %1, %2, %0;" : "+l"(d) : "l"(a), "l"(b));
}
__device__ __forceinline__ float2 unpack2(ull v) {
    float2 f; asm("mov.b64 {%0,%1}, %2;" : "=f"(f.x), "=f"(f.y) : "l"(v)); return f;
}

// ================= CSR build =================
__global__ void hist_kernel(const int* __restrict__ ei, int E, int* __restrict__ counts) {
    int e = blockIdx.x * blockDim.x + threadIdx.x;
    if (e < E) atomicAdd(&counts[ei[(size_t)E + e]], 1);
}

// single-block scan: per-thread serial chunk + one 1024-wide block scan
__global__ void scan_kernel(const int* __restrict__ counts, int N, int E,
                            int* __restrict__ offs, int* __restrict__ cursor) {
    __shared__ int sm[1024];
    const int tid = threadIdx.x;
    const int chunk = (N + 1023) / 1024;
    const int lo = tid * chunk;
    const int hi = min(lo + chunk, N);
    int s = 0;
    for (int i = lo; i < hi; i++) s += counts[i];
    sm[tid] = s;
    __syncthreads();
    for (int off = 1; off < 1024; off <<= 1) {
        int t = (tid >= off) ? sm[tid - off] : 0;
        __syncthreads();
        sm[tid] += t;
        __syncthreads();
    }
    int run = sm[tid] - s;  // exclusive prefix of this thread's chunk
    for (int i = lo; i < hi; i++) {
        int c = counts[i];
        offs[i] = run; cursor[i] = run;
        run += c;
    }
    if (tid == 0) offs[N] = E;
}

__global__ void fill_kernel(const int* __restrict__ ei, int E,
                            int* __restrict__ cursor, int* __restrict__ csr_src) {
    int e = blockIdx.x * blockDim.x + threadIdx.x;
    if (e < E) {
        int d = ei[(size_t)E + e];
        int pos = atomicAdd(&cursor[d], 1);
        csr_src[pos] = ei[e];
    }
}

// ================= fused layer: gather + GIN MLP =================
// W stored transposed + XOR-swizzled: element (c,k) at word
//   c*128 + 4*((k>>2) ^ ((c>>2)&31)) + (k&3)
// so a k-quad LDS.128 for col c=4*lane+j reads chunk (kq ^ lane): conflict-free.
__global__ void __launch_bounds__(FUSED_THREADS, 1) fused_layer_kernel(
    const float4* __restrict__ x4,
    const float* __restrict__ W1, const float* __restrict__ b1,
    const float* __restrict__ W2, const float* __restrict__ b2,
    const int* __restrict__ offs, const int* __restrict__ csr,
    float* __restrict__ xout, int n, int ntiles)
{
    extern __shared__ float smem[];
    float* W1s  = smem;                 // 16384 floats (transposed + swizzled)
    float* W2s  = W1s + 16384;          // 16384
    float* rows = W2s + 16384;          // 96*128 = 12288
    float* hs   = rows + 12288;         // 12288

    const int tid  = threadIdx.x;
    const int lane = tid & 31;
    const int wid  = tid >> 5;          // warp 0..11, owns rows wid*8..wid*8+7

    // ---- stage W1^T, W2^T with XOR swizzle ----
    {
        const float4* w1g = (const float4*)W1;
        const float4* w2g = (const float4*)W2;
        for (int i = tid; i < 4096; i += FUSED_THREADS) {
            int k = i >> 5, c4 = i & 31;   // element (k, c) for c = 4*c4+j
            float4 a = w1g[i];
            float4 b = w2g[i];
            int kq = k >> 2, kr = k & 3;
            #pragma unroll
            for (int j = 0; j < 4; j++) {
                int c = 4 * c4 + j;
                int addr = c * 128 + 4 * (kq ^ ((c >> 2) & 31)) + kr;
                float av = (j == 0) ? a.x : (j == 1) ? a.y : (j == 2) ? a.z : a.w;
                float bv = (j == 0) ? b.x : (j == 1) ? b.y : (j == 2) ? b.z : b.w;
                W1s[addr] = av;
                W2s[addr] = bv;
            }
        }
    }
    float bb1[4], bb2[4];
    #pragma unroll
    for (int j = 0; j < 4; j++) { bb1[j] = b1[lane * 4 + j]; bb2[j] = b2[lane * 4 + j]; }
    __syncthreads();

    for (int t = blockIdx.x; t < ntiles; t += gridDim.x) {
        const int row0 = t * TILE_ROWS;

        // ---- gather: warp wid fills rows[wid*8 .. wid*8+7] ----
        for (int rr = 0; rr < 8; rr++) {
            const int lr  = wid * 8 + rr;
            const int row = row0 + lr;
            float4 a = make_float4(0.f, 0.f, 0.f, 0.f);
            if (row < n) {
                a = x4[(size_t)row * 32 + lane];
                const int lo = offs[row];
                const int hi = offs[row + 1];
                for (int base = lo; base < hi; base += 32) {
                    int cnt = hi - base; if (cnt > 32) cnt = 32;
                    int idx = (lane < cnt) ? csr[base + lane] : 0;
                    int j = 0;
                    for (; j + 8 <= cnt; j += 8) {
                        int s0 = __shfl_sync(0xffffffffu, idx, j + 0);
                        int s1 = __shfl_sync(0xffffffffu, idx, j + 1);
                        int s2 = __shfl_sync(0xffffffffu, idx, j + 2);
                        int s3 = __shfl_sync(0xffffffffu, idx, j + 3);
                        int s4 = __shfl_sync(0xffffffffu, idx, j + 4);
                        int s5 = __shfl_sync(0xffffffffu, idx, j + 5);
                        int s6 = __shfl_sync(0xffffffffu, idx, j + 6);
                        int s7 = __shfl_sync(0xffffffffu, idx, j + 7);
                        float4 v0 = __ldg(x4 + (size_t)s0 * 32 + lane);
                        float4 v1 = __ldg(x4 + (size_t)s1 * 32 + lane);
                        float4 v2 = __ldg(x4 + (size_t)s2 * 32 + lane);
                        float4 v3 = __ldg(x4 + (size_t)s3 * 32 + lane);
                        float4 v4 = __ldg(x4 + (size_t)s4 * 32 + lane);
                        float4 v5 = __ldg(x4 + (size_t)s5 * 32 + lane);
                        float4 v6 = __ldg(x4 + (size_t)s6 * 32 + lane);
                        float4 v7 = __ldg(x4 + (size_t)s7 * 32 + lane);
                        a.x += v0.x + v1.x + v2.x + v3.x + v4.x + v5.x + v6.x + v7.x;
                        a.y += v0.y + v1.y + v2.y + v3.y + v4.y + v5.y + v6.y + v7.y;
                        a.z += v0.z + v1.z + v2.z + v3.z + v4.z + v5.z + v6.z + v7.z;
                        a.w += v0.w + v1.w + v2.w + v3.w + v4.w + v5.w + v6.w + v7.w;
                    }
                    for (; j < cnt; j++) {
                        int s = __shfl_sync(0xffffffffu, idx, j);
                        float4 v = __ldg(x4 + (size_t)s * 32 + lane);
                        a.x += v.x; a.y += v.y; a.z += v.z; a.w += v.w;
                    }
                }
            }
            *(float4*)(rows + lr * 128 + lane * 4) = a;
        }
        __syncthreads();

        // ---- GEMM1: hs = relu(rows @ W1 + b1) ----
        {
            ull acc[8][4];
            #pragma unroll
            for (int r = 0; r < 8; r++)
                #pragma unroll
                for (int j = 0; j < 4; j++) acc[r][j] = pack2(bb1[j], 0.f);

            const float* wb = W1s + (lane * 4) * 128;
            const float* rb = rows + (wid * 8) * 128;
            #pragma unroll 2
            for (int kq = 0; kq < 32; kq++) {
                const int ch = (kq ^ lane) << 2;
                ulonglong2 w0 = *(const ulonglong2*)(wb + ch);
                ulonglong2 w1 = *(const ulonglong2*)(wb + 128 + ch);
                ulonglong2 w2 = *(const ulonglong2*)(wb + 256 + ch);
                ulonglong2 w3 = *(const ulonglong2*)(wb + 384 + ch);
                #pragma unroll
                for (int r = 0; r < 8; r++) {
                    ulonglong2 v = *(const ulonglong2*)(rb + r * 128 + kq * 4);
                    fma2(acc[r][0], w0.x, v.x); fma2(acc[r][0], w0.y, v.y);
                    fma2(acc[r][1], w1.x, v.x); fma2(acc[r][1], w1.y, v.y);
                    fma2(acc[r][2], w2.x, v.x); fma2(acc[r][2], w2.y, v.y);
                    fma2(acc[r][3], w3.x, v.x); fma2(acc[r][3], w3.y, v.y);
                }
            }
            #pragma unroll
            for (int r = 0; r < 8; r++) {
                float2 p0 = unpack2(acc[r][0]);
                float2 p1 = unpack2(acc[r][1]);
                float2 p2 = unpack2(acc[r][2]);
                float2 p3 = unpack2(acc[r][3]);
                float4 h = make_float4(fmaxf(p0.x + p0.y, 0.f), fmaxf(p1.x + p1.y, 0.f),
                                       fmaxf(p2.x + p2.y, 0.f), fmaxf(p3.x + p3.y, 0.f));
                *(float4*)(hs + (wid * 8 + r) * 128 + lane * 4) = h;
            }
        }
        __syncthreads();

        // ---- GEMM2: xout = hs @ W2 + b2 ----
        {
            ull acc[8][4];
            #pragma unroll
            for (int r = 0; r < 8; r++)
                #pragma unroll
                for (int j = 0; j < 4; j++) acc[r][j] = pack2(bb2[j], 0.f);

            const float* wb = W2s + (lane * 4) * 128;
            const float* rb = hs + (wid * 8) * 128;
            #pragma unroll 2
            for (int kq = 0; kq < 32; kq++) {
                const int ch = (kq ^ lane) << 2;
                ulonglong2 w0 = *(const ulonglong2*)(wb + ch);
                ulonglong2 w1 = *(const ulonglong2*)(wb + 128 + ch);
                ulonglong2 w2 = *(const ulonglong2*)(wb + 256 + ch);
                ulonglong2 w3 = *(const ulonglong2*)(wb + 384 + ch);
                #pragma unroll
                for (int r = 0; r < 8; r++) {
                    ulonglong2 v = *(const ulonglong2*)(rb + r * 128 + kq * 4);
                    fma2(acc[r][0], w0.x, v.x); fma2(acc[r][0], w0.y, v.y);
                    fma2(acc[r][1], w1.x, v.x); fma2(acc[r][1], w1.y, v.y);
                    fma2(acc[r][2], w2.x, v.x); fma2(acc[r][2], w2.y, v.y);
                    fma2(acc[r][3], w3.x, v.x); fma2(acc[r][3], w3.y, v.y);
                }
            }
            #pragma unroll
            for (int r = 0; r < 8; r++) {
                int row = row0 + wid * 8 + r;
                if (row < n) {
                    float2 p0 = unpack2(acc[r][0]);
                    float2 p1 = unpack2(acc[r][1]);
                    float2 p2 = unpack2(acc[r][2]);
                    float2 p3 = unpack2(acc[r][3]);
                    *(float4*)(xout + (size_t)row * 128 + lane * 4) =
                        make_float4(p0.x + p0.y, p1.x + p1.y, p2.x + p2.y, p3.x + p3.y);
                }
            }
        }
        // no extra sync needed (see phase-ordering argument: the syncs after
        // gather and GEMM1 already order rows/hs rewrites across warps)
    }
}

// ================= readout =================
__device__ __forceinline__ int lower_bound_i(const int* __restrict__ a, int lo, int hi, int v) {
    while (lo < hi) {
        int m = (lo + hi) >> 1;
        if (a[m] < v) lo = m + 1; else hi = m;
    }
    return lo;
}

__global__ void readout_kernel(float* __restrict__ out, const float* __restrict__ xf,
                               const int* __restrict__ batch, int n) {
    const int g = blockIdx.x;
    const int j = threadIdx.x;
    int lo = lower_bound_i(batch, 0, n, g);
    int hi = lower_bound_i(batch, lo, n, g + 1);
    float s0 = 0.f, s1 = 0.f, s2 = 0.f, s3 = 0.f;
    int r = lo;
    for (; r + 4 <= hi; r += 4) {
        s0 += xf[(size_t)(r + 0) * D + j];
        s1 += xf[(size_t)(r + 1) * D + j];
        s2 += xf[(size_t)(r + 2) * D + j];
        s3 += xf[(size_t)(r + 3) * D + j];
    }
    for (; r < hi; r++) s0 += xf[(size_t)r * D + j];
    out[(size_t)g * D + j] = (s0 + s1) + (s2 + s3);
}

// ================= launch =================
extern "C" void kernel_launch(void* const* d_in, const int* in_sizes, int n_in,
                              void* d_out, int out_size) {
    const float* x   = (const float*)d_in[0];
    const float* W1  = (const float*)d_in[1];
    const float* b1  = (const float*)d_in[2];
    const float* W2  = (const float*)d_in[3];
    const float* b2  = (const float*)d_in[4];
    const int* ei    = (const int*)d_in[5];
    const int* bat   = (const int*)d_in[6];
    float* out       = (float*)d_out;

    const int N = in_sizes[0] / D;
    const int E = in_sizes[5] / 2;
    const int n_layers = in_sizes[1] / (D * D);

    float *xA, *xB;
    int *counts, *offs, *cursor, *csr;
    cudaGetSymbolAddress((void**)&xA, g_xA);
    cudaGetSymbolAddress((void**)&xB, g_xB);
    cudaGetSymbolAddress((void**)&counts, g_counts);
    cudaGetSymbolAddress((void**)&offs, g_offs);
    cudaGetSymbolAddress((void**)&cursor, g_cursor);
    cudaGetSymbolAddress((void**)&csr, g_csr_src);

    const int smem_bytes = (16384 * 2 + 12288 * 2) * 4;  // 229376
    cudaFuncSetAttribute(fused_layer_kernel, cudaFuncAttributeMaxDynamicSharedMemorySize, smem_bytes);

    // ---- CSR build ----
    cudaMemsetAsync(counts, 0, (size_t)N * sizeof(int), 0);  // not a kernel launch
    hist_kernel<<<(E + 255) / 256, 256>>>(ei, E, counts);    // launch 1
    scan_kernel<<<1, 1024>>>(counts, N, E, offs, cursor);    // launch 2
    fill_kernel<<<(E + 255) / 256, 256>>>(ei, E, cursor, csr); // launch 3

    // ---- layers: launch 4 (profiled), 5, 6 ----
    const int ntiles = (N + TILE_ROWS - 1) / TILE_ROWS;
    const float* xin = x;
    float* bufs[2] = { xA, xB };

    for (int l = 0; l < n_layers; l++) {
        fused_layer_kernel<<<148, FUSED_THREADS, smem_bytes>>>(
            (const float4*)xin,
            W1 + (size_t)l * D * D, b1 + (size_t)l * D,
            W2 + (size_t)l * D * D, b2 + (size_t)l * D,
            offs, csr, bufs[l & 1], N, ntiles);
        xin = bufs[l & 1];
    }

    readout_kernel<<<128, D>>>(out, xin, bat, N);
}

// round 6
// speedup vs baseline: 1.0331x; 1.0331x over previous
#include <cuda_runtime.h>
#include <cuda_bf16.h>
#include <cstdint>

#define D 128
#define TILE_ROWS 96
#define FUSED_THREADS 512
#define ROWS_PER_WARP 6

typedef unsigned long long ull;

// -------- scratch (no cudaMalloc allowed) --------
#define MAX_NODES 100000
#define MAX_EDGES 1600000
__device__ float g_xA[(size_t)MAX_NODES * D];
__device__ float g_xB[(size_t)MAX_NODES * D];
__device__ int   g_counts[MAX_NODES];
__device__ int   g_offs[MAX_NODES + 1];
__device__ int   g_cursor[MAX_NODES];
__device__ int   g_csr_src[MAX_EDGES];

// -------- packed fp32x2 helpers (Blackwell FFMA2) --------
__device__ __forceinline__ ull pack2(float lo, float hi) {
    ull r; asm("mov.b64 %0, {%1,%2};" : "=l"(r) : "f"(lo), "f"(hi)); return r;
}
__device__ __forceinline__ void fma2(ull &d, ull a, ull b) {
    asm("fma.rn.f32x2 %0, %1, %2, %0;" : "+l"(d) : "l"(a), "l"(b));
}
__device__ __forceinline__ float2 unpack2(ull v) {
    float2 f; asm("mov.b64 {%0,%1}, %2;" : "=f"(f.x), "=f"(f.y) : "l"(v)); return f;
}

// ================= CSR build =================
__global__ void hist_kernel(const int* __restrict__ ei, int E, int* __restrict__ counts) {
    int e = blockIdx.x * blockDim.x + threadIdx.x;
    if (e < E) atomicAdd(&counts[ei[(size_t)E + e]], 1);
}

__global__ void scan_kernel(const int* __restrict__ counts, int N, int E,
                            int* __restrict__ offs, int* __restrict__ cursor) {
    __shared__ int sm[1024];
    const int tid = threadIdx.x;
    const int chunk = (N + 1023) / 1024;
    const int lo = tid * chunk;
    const int hi = min(lo + chunk, N);
    int s = 0;
    for (int i = lo; i < hi; i++) s += counts[i];
    sm[tid] = s;
    __syncthreads();
    for (int off = 1; off < 1024; off <<= 1) {
        int t = (tid >= off) ? sm[tid - off] : 0;
        __syncthreads();
        sm[tid] += t;
        __syncthreads();
    }
    int run = sm[tid] - s;
    for (int i = lo; i < hi; i++) {
        int c = counts[i];
        offs[i] = run; cursor[i] = run;
        run += c;
    }
    if (tid == 0) offs[N] = E;
}

__global__ void fill_kernel(const int* __restrict__ ei, int E,
                            int* __restrict__ cursor, int* __restrict__ csr_src) {
    int e = blockIdx.x * blockDim.x + threadIdx.x;
    if (e < E) {
        int d = ei[(size_t)E + e];
        int pos = atomicAdd(&cursor[d], 1);
        csr_src[pos] = ei[e];
    }
}

// ================= fused layer: gather + GIN MLP =================
// W stored transposed + XOR-swizzled: element (c,k) at word
//   c*128 + 4*((k>>2) ^ ((c>>2)&31)) + (k&3)
// so a k-quad LDS.128 for col c=4*lane+j reads chunk (kq ^ lane): conflict-free.
// FFMA2 scheduling: rows processed in pairs with x-pass/x-pass/y-pass/y-pass
// interleave -> each accumulator reused at distance 8 instrs (no RAW stall).
__global__ void __launch_bounds__(FUSED_THREADS, 1) fused_layer_kernel(
    const float4* __restrict__ x4,
    const float* __restrict__ W1, const float* __restrict__ b1,
    const float* __restrict__ W2, const float* __restrict__ b2,
    const int* __restrict__ offs, const int* __restrict__ csr,
    float* __restrict__ xout, int n, int ntiles)
{
    extern __shared__ float smem[];
    float* W1s  = smem;                 // 16384 floats (transposed + swizzled)
    float* W2s  = W1s + 16384;          // 16384
    float* rows = W2s + 16384;          // 96*128 = 12288
    float* hs   = rows + 12288;         // 12288

    const int tid  = threadIdx.x;
    const int lane = tid & 31;
    const int wid  = tid >> 5;          // warp 0..15, owns rows wid*6..wid*6+5

    // ---- stage W1^T, W2^T with XOR swizzle ----
    {
        const float4* w1g = (const float4*)W1;
        const float4* w2g = (const float4*)W2;
        for (int i = tid; i < 4096; i += FUSED_THREADS) {
            int k = i >> 5, c4 = i & 31;   // element (k, c) for c = 4*c4+j
            float4 a = w1g[i];
            float4 b = w2g[i];
            int kq = k >> 2, kr = k & 3;
            #pragma unroll
            for (int j = 0; j < 4; j++) {
                int c = 4 * c4 + j;
                int addr = c * 128 + 4 * (kq ^ ((c >> 2) & 31)) + kr;
                float av = (j == 0) ? a.x : (j == 1) ? a.y : (j == 2) ? a.z : a.w;
                float bv = (j == 0) ? b.x : (j == 1) ? b.y : (j == 2) ? b.z : b.w;
                W1s[addr] = av;
                W2s[addr] = bv;
            }
        }
    }
    float bb1[4], bb2[4];
    #pragma unroll
    for (int j = 0; j < 4; j++) { bb1[j] = b1[lane * 4 + j]; bb2[j] = b2[lane * 4 + j]; }
    __syncthreads();

    for (int t = blockIdx.x; t < ntiles; t += gridDim.x) {
        const int row0 = t * TILE_ROWS;

        // ---- gather: warp wid fills rows[wid*6 .. wid*6+5] ----
        for (int rr = 0; rr < ROWS_PER_WARP; rr++) {
            const int lr  = wid * ROWS_PER_WARP + rr;
            const int row = row0 + lr;
            float4 a = make_float4(0.f, 0.f, 0.f, 0.f);
            if (row < n) {
                a = x4[(size_t)row * 32 + lane];
                const int lo = offs[row];
                const int hi = offs[row + 1];
                for (int base = lo; base < hi; base += 32) {
                    int cnt = hi - base; if (cnt > 32) cnt = 32;
                    int idx = (lane < cnt) ? csr[base + lane] : 0;
                    int j = 0;
                    for (; j + 8 <= cnt; j += 8) {
                        int s0 = __shfl_sync(0xffffffffu, idx, j + 0);
                        int s1 = __shfl_sync(0xffffffffu, idx, j + 1);
                        int s2 = __shfl_sync(0xffffffffu, idx, j + 2);
                        int s3 = __shfl_sync(0xffffffffu, idx, j + 3);
                        int s4 = __shfl_sync(0xffffffffu, idx, j + 4);
                        int s5 = __shfl_sync(0xffffffffu, idx, j + 5);
                        int s6 = __shfl_sync(0xffffffffu, idx, j + 6);
                        int s7 = __shfl_sync(0xffffffffu, idx, j + 7);
                        float4 v0 = __ldg(x4 + (size_t)s0 * 32 + lane);
                        float4 v1 = __ldg(x4 + (size_t)s1 * 32 + lane);
                        float4 v2 = __ldg(x4 + (size_t)s2 * 32 + lane);
                        float4 v3 = __ldg(x4 + (size_t)s3 * 32 + lane);
                        float4 v4 = __ldg(x4 + (size_t)s4 * 32 + lane);
                        float4 v5 = __ldg(x4 + (size_t)s5 * 32 + lane);
                        float4 v6 = __ldg(x4 + (size_t)s6 * 32 + lane);
                        float4 v7 = __ldg(x4 + (size_t)s7 * 32 + lane);
                        a.x += v0.x + v1.x + v2.x + v3.x + v4.x + v5.x + v6.x + v7.x;
                        a.y += v0.y + v1.y + v2.y + v3.y + v4.y + v5.y + v6.y + v7.y;
                        a.z += v0.z + v1.z + v2.z + v3.z + v4.z + v5.z + v6.z + v7.z;
                        a.w += v0.w + v1.w + v2.w + v3.w + v4.w + v5.w + v6.w + v7.w;
                    }
                    for (; j < cnt; j++) {
                        int s = __shfl_sync(0xffffffffu, idx, j);
                        float4 v = __ldg(x4 + (size_t)s * 32 + lane);
                        a.x += v.x; a.y += v.y; a.z += v.z; a.w += v.w;
                    }
                }
            }
            *(float4*)(rows + lr * 128 + lane * 4) = a;
        }
        __syncthreads();

        // ---- GEMM1: hs = relu(rows @ W1 + b1) ----
        {
            ull acc[ROWS_PER_WARP][4];
            #pragma unroll
            for (int r = 0; r < ROWS_PER_WARP; r++)
                #pragma unroll
                for (int j = 0; j < 4; j++) acc[r][j] = pack2(bb1[j], 0.f);

            const float* wb = W1s + (lane * 4) * 128;
            const float* rb = rows + (wid * ROWS_PER_WARP) * 128;
            #pragma unroll 2
            for (int kq = 0; kq < 32; kq++) {
                const int ch = (kq ^ lane) << 2;
                ulonglong2 w0 = *(const ulonglong2*)(wb + ch);
                ulonglong2 w1 = *(const ulonglong2*)(wb + 128 + ch);
                ulonglong2 w2 = *(const ulonglong2*)(wb + 256 + ch);
                ulonglong2 w3 = *(const ulonglong2*)(wb + 384 + ch);
                #pragma unroll
                for (int r = 0; r < ROWS_PER_WARP; r += 2) {
                    ulonglong2 va = *(const ulonglong2*)(rb + r * 128 + kq * 4);
                    ulonglong2 vb = *(const ulonglong2*)(rb + (r + 1) * 128 + kq * 4);
                    // x-pass row r, x-pass row r+1, y-pass row r, y-pass row r+1
                    fma2(acc[r][0], w0.x, va.x); fma2(acc[r][1], w1.x, va.x);
                    fma2(acc[r][2], w2.x, va.x); fma2(acc[r][3], w3.x, va.x);
                    fma2(acc[r+1][0], w0.x, vb.x); fma2(acc[r+1][1], w1.x, vb.x);
                    fma2(acc[r+1][2], w2.x, vb.x); fma2(acc[r+1][3], w3.x, vb.x);
                    fma2(acc[r][0], w0.y, va.y); fma2(acc[r][1], w1.y, va.y);
                    fma2(acc[r][2], w2.y, va.y); fma2(acc[r][3], w3.y, va.y);
                    fma2(acc[r+1][0], w0.y, vb.y); fma2(acc[r+1][1], w1.y, vb.y);
                    fma2(acc[r+1][2], w2.y, vb.y); fma2(acc[r+1][3], w3.y, vb.y);
                }
            }
            #pragma unroll
            for (int r = 0; r < ROWS_PER_WARP; r++) {
                float2 p0 = unpack2(acc[r][0]);
                float2 p1 = unpack2(acc[r][1]);
                float2 p2 = unpack2(acc[r][2]);
                float2 p3 = unpack2(acc[r][3]);
                float4 h = make_float4(fmaxf(p0.x + p0.y, 0.f), fmaxf(p1.x + p1.y, 0.f),
                                       fmaxf(p2.x + p2.y, 0.f), fmaxf(p3.x + p3.y, 0.f));
                *(float4*)(hs + (wid * ROWS_PER_WARP + r) * 128 + lane * 4) = h;
            }
        }
        __syncthreads();

        // ---- GEMM2: xout = hs @ W2 + b2 ----
        {
            ull acc[ROWS_PER_WARP][4];
            #pragma unroll
            for (int r = 0; r < ROWS_PER_WARP; r++)
                #pragma unroll
                for (int j = 0; j < 4; j++) acc[r][j] = pack2(bb2[j], 0.f);

            const float* wb = W2s + (lane * 4) * 128;
            const float* rb = hs + (wid * ROWS_PER_WARP) * 128;
            #pragma unroll 2
            for (int kq = 0; kq < 32; kq++) {
                const int ch = (kq ^ lane) << 2;
                ulonglong2 w0 = *(const ulonglong2*)(wb + ch);
                ulonglong2 w1 = *(const ulonglong2*)(wb + 128 + ch);
                ulonglong2 w2 = *(const ulonglong2*)(wb + 256 + ch);
                ulonglong2 w3 = *(const ulonglong2*)(wb + 384 + ch);
                #pragma unroll
                for (int r = 0; r < ROWS_PER_WARP; r += 2) {
                    ulonglong2 va = *(const ulonglong2*)(rb + r * 128 + kq * 4);
                    ulonglong2 vb = *(const ulonglong2*)(rb + (r + 1) * 128 + kq * 4);
                    fma2(acc[r][0], w0.x, va.x); fma2(acc[r][1], w1.x, va.x);
                    fma2(acc[r][2], w2.x, va.x); fma2(acc[r][3], w3.x, va.x);
                    fma2(acc[r+1][0], w0.x, vb.x); fma2(acc[r+1][1], w1.x, vb.x);
                    fma2(acc[r+1][2], w2.x, vb.x); fma2(acc[r+1][3], w3.x, vb.x);
                    fma2(acc[r][0], w0.y, va.y); fma2(acc[r][1], w1.y, va.y);
                    fma2(acc[r][2], w2.y, va.y); fma2(acc[r][3], w3.y, va.y);
                    fma2(acc[r+1][0], w0.y, vb.y); fma2(acc[r+1][1], w1.y, vb.y);
                    fma2(acc[r+1][2], w2.y, vb.y); fma2(acc[r+1][3], w3.y, vb.y);
                }
            }
            #pragma unroll
            for (int r = 0; r < ROWS_PER_WARP; r++) {
                int row = row0 + wid * ROWS_PER_WARP + r;
                if (row < n) {
                    float2 p0 = unpack2(acc[r][0]);
                    float2 p1 = unpack2(acc[r][1]);
                    float2 p2 = unpack2(acc[r][2]);
                    float2 p3 = unpack2(acc[r][3]);
                    *(float4*)(xout + (size_t)row * 128 + lane * 4) =
                        make_float4(p0.x + p0.y, p1.x + p1.y, p2.x + p2.y, p3.x + p3.y);
                }
            }
        }
        // phase-ordering: syncs after gather and GEMM1 already order the
        // rows/hs rewrites across warps; no sync needed here.
    }
}

// ================= readout =================
__device__ __forceinline__ int lower_bound_i(const int* __restrict__ a, int lo, int hi, int v) {
    while (lo < hi) {
        int m = (lo + hi) >> 1;
        if (a[m] < v) lo = m + 1; else hi = m;
    }
    return lo;
}

__global__ void readout_kernel(float* __restrict__ out, const float* __restrict__ xf,
                               const int* __restrict__ batch, int n) {
    const int g = blockIdx.x;
    const int j = threadIdx.x;
    int lo = lower_bound_i(batch, 0, n, g);
    int hi = lower_bound_i(batch, lo, n, g + 1);
    float s0 = 0.f, s1 = 0.f, s2 = 0.f, s3 = 0.f;
    int r = lo;
    for (; r + 4 <= hi; r += 4) {
        s0 += xf[(size_t)(r + 0) * D + j];
        s1 += xf[(size_t)(r + 1) * D + j];
        s2 += xf[(size_t)(r + 2) * D + j];
        s3 += xf[(size_t)(r + 3) * D + j];
    }
    for (; r < hi; r++) s0 += xf[(size_t)r * D + j];
    out[(size_t)g * D + j] = (s0 + s1) + (s2 + s3);
}

// ================= launch =================
extern "C" void kernel_launch(void* const* d_in, const int* in_sizes, int n_in,
                              void* d_out, int out_size) {
    const float* x   = (const float*)d_in[0];
    const float* W1  = (const float*)d_in[1];
    const float* b1  = (const float*)d_in[2];
    const float* W2  = (const float*)d_in[3];
    const float* b2  = (const float*)d_in[4];
    const int* ei    = (const int*)d_in[5];
    const int* bat   = (const int*)d_in[6];
    float* out       = (float*)d_out;

    const int N = in_sizes[0] / D;
    const int E = in_sizes[5] / 2;
    const int n_layers = in_sizes[1] / (D * D);

    float *xA, *xB;
    int *counts, *offs, *cursor, *csr;
    cudaGetSymbolAddress((void**)&xA, g_xA);
    cudaGetSymbolAddress((void**)&xB, g_xB);
    cudaGetSymbolAddress((void**)&counts, g_counts);
    cudaGetSymbolAddress((void**)&offs, g_offs);
    cudaGetSymbolAddress((void**)&cursor, g_cursor);
    cudaGetSymbolAddress((void**)&csr, g_csr_src);

    const int smem_bytes = (16384 * 2 + 12288 * 2) * 4;  // 229376
    cudaFuncSetAttribute(fused_layer_kernel, cudaFuncAttributeMaxDynamicSharedMemorySize, smem_bytes);

    // ---- CSR build ----
    cudaMemsetAsync(counts, 0, (size_t)N * sizeof(int), 0);
    hist_kernel<<<(E + 255) / 256, 256>>>(ei, E, counts);      // launch 1
    scan_kernel<<<1, 1024>>>(counts, N, E, offs, cursor);      // launch 2
    fill_kernel<<<(E + 255) / 256, 256>>>(ei, E, cursor, csr); // launch 3

    // ---- layers: launch 4 (profiled), 5, 6 ----
    const int ntiles = (N + TILE_ROWS - 1) / TILE_ROWS;
    const float* xin = x;
    float* bufs[2] = { xA, xB };

    for (int l = 0; l < n_layers; l++) {
        fused_layer_kernel<<<148, FUSED_THREADS, smem_bytes>>>(
            (const float4*)xin,
            W1 + (size_t)l * D * D, b1 + (size_t)l * D,
            W2 + (size_t)l * D * D, b2 + (size_t)l * D,
            offs, csr, bufs[l & 1], N, ntiles);
        xin = bufs[l & 1];
    }

    readout_kernel<<<128, D>>>(out, xin, bat, N);
}

// round 7
// speedup vs baseline: 1.1506x; 1.1137x over previous
#include <cuda_runtime.h>
#include <cuda_bf16.h>
#include <cstdint>

#define D 128
#define TILE_ROWS 96
#define FUSED_THREADS 512
#define ROWS_PER_WARP 6

typedef unsigned long long ull;

// -------- scratch (no cudaMalloc allowed) --------
#define MAX_NODES 100000
#define MAX_EDGES 1600000
__device__ float g_xA[(size_t)MAX_NODES * D];
__device__ float g_xB[(size_t)MAX_NODES * D];
__device__ int   g_counts[MAX_NODES];
__device__ int   g_offs[MAX_NODES + 1];
__device__ int   g_cursor[MAX_NODES];
__device__ int   g_csr_src[MAX_EDGES];

// -------- packed fp32x2 helpers (Blackwell FFMA2) --------
__device__ __forceinline__ ull pack2(float lo, float hi) {
    ull r; asm("mov.b64 %0, {%1,%2};" : "=l"(r) : "f"(lo), "f"(hi)); return r;
}
__device__ __forceinline__ void fma2(ull &d, ull a, ull b) {
    asm("fma.rn.f32x2 %0, %1, %2, %0;" : "+l"(d) : "l"(a), "l"(b));
}
__device__ __forceinline__ float2 unpack2(ull v) {
    float2 f; asm("mov.b64 {%0,%1}, %2;" : "=f"(f.x), "=f"(f.y) : "l"(v)); return f;
}

// ================= CSR build =================
__global__ void hist_kernel(const int* __restrict__ ei, int E, int* __restrict__ counts) {
    int e = blockIdx.x * blockDim.x + threadIdx.x;
    if (e < E) atomicAdd(&counts[ei[(size_t)E + e]], 1);
}

__global__ void scan_kernel(const int* __restrict__ counts, int N, int E,
                            int* __restrict__ offs, int* __restrict__ cursor) {
    __shared__ int sm[1024];
    const int tid = threadIdx.x;
    const int chunk = (N + 1023) / 1024;
    const int lo = tid * chunk;
    const int hi = min(lo + chunk, N);
    int s = 0;
    for (int i = lo; i < hi; i++) s += counts[i];
    sm[tid] = s;
    __syncthreads();
    for (int off = 1; off < 1024; off <<= 1) {
        int t = (tid >= off) ? sm[tid - off] : 0;
        __syncthreads();
        sm[tid] += t;
        __syncthreads();
    }
    int run = sm[tid] - s;
    for (int i = lo; i < hi; i++) {
        int c = counts[i];
        offs[i] = run; cursor[i] = run;
        run += c;
    }
    if (tid == 0) offs[N] = E;
}

__global__ void fill_kernel(const int* __restrict__ ei, int E,
                            int* __restrict__ cursor, int* __restrict__ csr_src) {
    int e = blockIdx.x * blockDim.x + threadIdx.x;
    if (e < E) {
        int d = ei[(size_t)E + e];
        int pos = atomicAdd(&cursor[d], 1);
        csr_src[pos] = ei[e];
    }
}

// ================= fused layer: gather + GIN MLP (warp-autonomous) =================
// KEY INSIGHT: rows[wid*6..wid*6+5] and hs[wid*6..wid*6+5] are warp-private
// (produced and consumed only by warp wid). Only W1s/W2s is block-shared and
// read-only after init. So the tile loop needs NO __syncthreads — only
// __syncwarp() to order cross-lane STS->LDS. Warps flow independently: one
// warp's L2-bound gather overlaps other warps' FFMA2 on the same SMSP.
__global__ void __launch_bounds__(FUSED_THREADS, 1) fused_layer_kernel(
    const float4* __restrict__ x4,
    const float* __restrict__ W1, const float* __restrict__ b1,
    const float* __restrict__ W2, const float* __restrict__ b2,
    const int* __restrict__ offs, const int* __restrict__ csr,
    float* __restrict__ xout, int n, int ntiles)
{
    extern __shared__ float smem[];
    float* W1s  = smem;                 // 16384 floats (transposed + swizzled)
    float* W2s  = W1s + 16384;          // 16384
    float* rows = W2s + 16384;          // 96*128 = 12288
    float* hs   = rows + 12288;         // 12288

    const int tid  = threadIdx.x;
    const int lane = tid & 31;
    const int wid  = tid >> 5;          // warp 0..15, owns rows wid*6..wid*6+5

    // ---- stage W1^T, W2^T with XOR swizzle: element (c,k) at word
    //      c*128 + 4*((k>>2) ^ ((c>>2)&31)) + (k&3)  -> conflict-free LDS.128 ----
    {
        const float4* w1g = (const float4*)W1;
        const float4* w2g = (const float4*)W2;
        for (int i = tid; i < 4096; i += FUSED_THREADS) {
            int k = i >> 5, c4 = i & 31;
            float4 a = w1g[i];
            float4 b = w2g[i];
            int kq = k >> 2, kr = k & 3;
            #pragma unroll
            for (int j = 0; j < 4; j++) {
                int c = 4 * c4 + j;
                int addr = c * 128 + 4 * (kq ^ ((c >> 2) & 31)) + kr;
                float av = (j == 0) ? a.x : (j == 1) ? a.y : (j == 2) ? a.z : a.w;
                float bv = (j == 0) ? b.x : (j == 1) ? b.y : (j == 2) ? b.z : b.w;
                W1s[addr] = av;
                W2s[addr] = bv;
            }
        }
    }
    float bb1[4], bb2[4];
    #pragma unroll
    for (int j = 0; j < 4; j++) { bb1[j] = b1[lane * 4 + j]; bb2[j] = b2[lane * 4 + j]; }
    __syncthreads();   // everyone sees W before any warp starts computing

    for (int t = blockIdx.x; t < ntiles; t += gridDim.x) {
        const int row0 = t * TILE_ROWS;

        // ---- gather: warp wid fills its private rows[wid*6 .. wid*6+5] ----
        for (int rr = 0; rr < ROWS_PER_WARP; rr++) {
            const int lr  = wid * ROWS_PER_WARP + rr;
            const int row = row0 + lr;
            float4 a = make_float4(0.f, 0.f, 0.f, 0.f);
            if (row < n) {
                a = x4[(size_t)row * 32 + lane];
                const int lo = offs[row];
                const int hi = offs[row + 1];
                for (int base = lo; base < hi; base += 32) {
                    int cnt = hi - base; if (cnt > 32) cnt = 32;
                    int idx = (lane < cnt) ? csr[base + lane] : 0;
                    int j = 0;
                    for (; j + 8 <= cnt; j += 8) {
                        int s0 = __shfl_sync(0xffffffffu, idx, j + 0);
                        int s1 = __shfl_sync(0xffffffffu, idx, j + 1);
                        int s2 = __shfl_sync(0xffffffffu, idx, j + 2);
                        int s3 = __shfl_sync(0xffffffffu, idx, j + 3);
                        int s4 = __shfl_sync(0xffffffffu, idx, j + 4);
                        int s5 = __shfl_sync(0xffffffffu, idx, j + 5);
                        int s6 = __shfl_sync(0xffffffffu, idx, j + 6);
                        int s7 = __shfl_sync(0xffffffffu, idx, j + 7);
                        float4 v0 = __ldg(x4 + (size_t)s0 * 32 + lane);
                        float4 v1 = __ldg(x4 + (size_t)s1 * 32 + lane);
                        float4 v2 = __ldg(x4 + (size_t)s2 * 32 + lane);
                        float4 v3 = __ldg(x4 + (size_t)s3 * 32 + lane);
                        float4 v4 = __ldg(x4 + (size_t)s4 * 32 + lane);
                        float4 v5 = __ldg(x4 + (size_t)s5 * 32 + lane);
                        float4 v6 = __ldg(x4 + (size_t)s6 * 32 + lane);
                        float4 v7 = __ldg(x4 + (size_t)s7 * 32 + lane);
                        a.x += v0.x + v1.x + v2.x + v3.x + v4.x + v5.x + v6.x + v7.x;
                        a.y += v0.y + v1.y + v2.y + v3.y + v4.y + v5.y + v6.y + v7.y;
                        a.z += v0.z + v1.z + v2.z + v3.z + v4.z + v5.z + v6.z + v7.z;
                        a.w += v0.w + v1.w + v2.w + v3.w + v4.w + v5.w + v6.w + v7.w;
                    }
                    for (; j < cnt; j++) {
                        int s = __shfl_sync(0xffffffffu, idx, j);
                        float4 v = __ldg(x4 + (size_t)s * 32 + lane);
                        a.x += v.x; a.y += v.y; a.z += v.z; a.w += v.w;
                    }
                }
            }
            *(float4*)(rows + lr * 128 + lane * 4) = a;
        }
        __syncwarp();   // order cross-lane rows STS -> GEMM1 LDS (warp-local)

        // ---- GEMM1: hs = relu(rows @ W1 + b1) ----
        {
            ull acc[ROWS_PER_WARP][4];
            #pragma unroll
            for (int r = 0; r < ROWS_PER_WARP; r++)
                #pragma unroll
                for (int j = 0; j < 4; j++) acc[r][j] = pack2(bb1[j], 0.f);

            const float* wb = W1s + (lane * 4) * 128;
            const float* rb = rows + (wid * ROWS_PER_WARP) * 128;
            #pragma unroll 2
            for (int kq = 0; kq < 32; kq++) {
                const int ch = (kq ^ lane) << 2;
                ulonglong2 w0 = *(const ulonglong2*)(wb + ch);
                ulonglong2 w1 = *(const ulonglong2*)(wb + 128 + ch);
                ulonglong2 w2 = *(const ulonglong2*)(wb + 256 + ch);
                ulonglong2 w3 = *(const ulonglong2*)(wb + 384 + ch);
                #pragma unroll
                for (int r = 0; r < ROWS_PER_WARP; r += 2) {
                    ulonglong2 va = *(const ulonglong2*)(rb + r * 128 + kq * 4);
                    ulonglong2 vb = *(const ulonglong2*)(rb + (r + 1) * 128 + kq * 4);
                    fma2(acc[r][0], w0.x, va.x); fma2(acc[r][1], w1.x, va.x);
                    fma2(acc[r][2], w2.x, va.x); fma2(acc[r][3], w3.x, va.x);
                    fma2(acc[r+1][0], w0.x, vb.x); fma2(acc[r+1][1], w1.x, vb.x);
                    fma2(acc[r+1][2], w2.x, vb.x); fma2(acc[r+1][3], w3.x, vb.x);
                    fma2(acc[r][0], w0.y, va.y); fma2(acc[r][1], w1.y, va.y);
                    fma2(acc[r][2], w2.y, va.y); fma2(acc[r][3], w3.y, va.y);
                    fma2(acc[r+1][0], w0.y, vb.y); fma2(acc[r+1][1], w1.y, vb.y);
                    fma2(acc[r+1][2], w2.y, vb.y); fma2(acc[r+1][3], w3.y, vb.y);
                }
            }
            #pragma unroll
            for (int r = 0; r < ROWS_PER_WARP; r++) {
                float2 p0 = unpack2(acc[r][0]);
                float2 p1 = unpack2(acc[r][1]);
                float2 p2 = unpack2(acc[r][2]);
                float2 p3 = unpack2(acc[r][3]);
                float4 h = make_float4(fmaxf(p0.x + p0.y, 0.f), fmaxf(p1.x + p1.y, 0.f),
                                       fmaxf(p2.x + p2.y, 0.f), fmaxf(p3.x + p3.y, 0.f));
                *(float4*)(hs + (wid * ROWS_PER_WARP + r) * 128 + lane * 4) = h;
            }
        }
        __syncwarp();   // order hs STS -> GEMM2 LDS; also fences this tile's
                        // rows reads before next tile's gather rewrites them

        // ---- GEMM2: xout = hs @ W2 + b2 ----
        {
            ull acc[ROWS_PER_WARP][4];
            #pragma unroll
            for (int r = 0; r < ROWS_PER_WARP; r++)
                #pragma unroll
                for (int j = 0; j < 4; j++) acc[r][j] = pack2(bb2[j], 0.f);

            const float* wb = W2s + (lane * 4) * 128;
            const float* rb = hs + (wid * ROWS_PER_WARP) * 128;
            #pragma unroll 2
            for (int kq = 0; kq < 32; kq++) {
                const int ch = (kq ^ lane) << 2;
                ulonglong2 w0 = *(const ulonglong2*)(wb + ch);
                ulonglong2 w1 = *(const ulonglong2*)(wb + 128 + ch);
                ulonglong2 w2 = *(const ulonglong2*)(wb + 256 + ch);
                ulonglong2 w3 = *(const ulonglong2*)(wb + 384 + ch);
                #pragma unroll
                for (int r = 0; r < ROWS_PER_WARP; r += 2) {
                    ulonglong2 va = *(const ulonglong2*)(rb + r * 128 + kq * 4);
                    ulonglong2 vb = *(const ulonglong2*)(rb + (r + 1) * 128 + kq * 4);
                    fma2(acc[r][0], w0.x, va.x); fma2(acc[r][1], w1.x, va.x);
                    fma2(acc[r][2], w2.x, va.x); fma2(acc[r][3], w3.x, va.x);
                    fma2(acc[r+1][0], w0.x, vb.x); fma2(acc[r+1][1], w1.x, vb.x);
                    fma2(acc[r+1][2], w2.x, vb.x); fma2(acc[r+1][3], w3.x, vb.x);
                    fma2(acc[r][0], w0.y, va.y); fma2(acc[r][1], w1.y, va.y);
                    fma2(acc[r][2], w2.y, va.y); fma2(acc[r][3], w3.y, va.y);
                    fma2(acc[r+1][0], w0.y, vb.y); fma2(acc[r+1][1], w1.y, vb.y);
                    fma2(acc[r+1][2], w2.y, vb.y); fma2(acc[r+1][3], w3.y, vb.y);
                }
            }
            #pragma unroll
            for (int r = 0; r < ROWS_PER_WARP; r++) {
                int row = row0 + wid * ROWS_PER_WARP + r;
                if (row < n) {
                    float2 p0 = unpack2(acc[r][0]);
                    float2 p1 = unpack2(acc[r][1]);
                    float2 p2 = unpack2(acc[r][2]);
                    float2 p3 = unpack2(acc[r][3]);
                    *(float4*)(xout + (size_t)row * 128 + lane * 4) =
                        make_float4(p0.x + p0.y, p1.x + p1.y, p2.x + p2.y, p3.x + p3.y);
                }
            }
        }
        __syncwarp();   // fence hs reads before next tile's GEMM1 rewrites hs
    }
}

// ================= readout =================
__device__ __forceinline__ int lower_bound_i(const int* __restrict__ a, int lo, int hi, int v) {
    while (lo < hi) {
        int m = (lo + hi) >> 1;
        if (a[m] < v) lo = m + 1; else hi = m;
    }
    return lo;
}

__global__ void readout_kernel(float* __restrict__ out, const float* __restrict__ xf,
                               const int* __restrict__ batch, int n) {
    const int g = blockIdx.x;
    const int j = threadIdx.x;
    int lo = lower_bound_i(batch, 0, n, g);
    int hi = lower_bound_i(batch, lo, n, g + 1);
    float s0 = 0.f, s1 = 0.f, s2 = 0.f, s3 = 0.f;
    int r = lo;
    for (; r + 4 <= hi; r += 4) {
        s0 += xf[(size_t)(r + 0) * D + j];
        s1 += xf[(size_t)(r + 1) * D + j];
        s2 += xf[(size_t)(r + 2) * D + j];
        s3 += xf[(size_t)(r + 3) * D + j];
    }
    for (; r < hi; r++) s0 += xf[(size_t)r * D + j];
    out[(size_t)g * D + j] = (s0 + s1) + (s2 + s3);
}

// ================= launch =================
extern "C" void kernel_launch(void* const* d_in, const int* in_sizes, int n_in,
                              void* d_out, int out_size) {
    const float* x   = (const float*)d_in[0];
    const float* W1  = (const float*)d_in[1];
    const float* b1  = (const float*)d_in[2];
    const float* W2  = (const float*)d_in[3];
    const float* b2  = (const float*)d_in[4];
    const int* ei    = (const int*)d_in[5];
    const int* bat   = (const int*)d_in[6];
    float* out       = (float*)d_out;

    const int N = in_sizes[0] / D;
    const int E = in_sizes[5] / 2;
    const int n_layers = in_sizes[1] / (D * D);

    float *xA, *xB;
    int *counts, *offs, *cursor, *csr;
    cudaGetSymbolAddress((void**)&xA, g_xA);
    cudaGetSymbolAddress((void**)&xB, g_xB);
    cudaGetSymbolAddress((void**)&counts, g_counts);
    cudaGetSymbolAddress((void**)&offs, g_offs);
    cudaGetSymbolAddress((void**)&cursor, g_cursor);
    cudaGetSymbolAddress((void**)&csr, g_csr_src);

    const int smem_bytes = (16384 * 2 + 12288 * 2) * 4;  // 229376
    cudaFuncSetAttribute(fused_layer_kernel, cudaFuncAttributeMaxDynamicSharedMemorySize, smem_bytes);

    // ---- CSR build ----
    cudaMemsetAsync(counts, 0, (size_t)N * sizeof(int), 0);
    hist_kernel<<<(E + 255) / 256, 256>>>(ei, E, counts);      // launch 1
    scan_kernel<<<1, 1024>>>(counts, N, E, offs, cursor);      // launch 2
    fill_kernel<<<(E + 255) / 256, 256>>>(ei, E, cursor, csr); // launch 3

    // ---- layers: launch 4 (profiled), 5, 6 ----
    const int ntiles = (N + TILE_ROWS - 1) / TILE_ROWS;
    const float* xin = x;
    float* bufs[2] = { xA, xB };

    for (int l = 0; l < n_layers; l++) {
        fused_layer_kernel<<<148, FUSED_THREADS, smem_bytes>>>(
            (const float4*)xin,
            W1 + (size_t)l * D * D, b1 + (size_t)l * D,
            W2 + (size_t)l * D * D, b2 + (size_t)l * D,
            offs, csr, bufs[l & 1], N, ntiles);
        xin = bufs[l & 1];
    }

    readout_kernel<<<128, D>>>(out, xin, bat, N);
}